// round 6
// baseline (speedup 1.0000x reference)
#include <cuda_runtime.h>

// DistMult edge score: out[e] = sum_d node[src[e]][d] * rel[e][d] * node[dst[e]][d]
// N_NODES=100000, N_EDGES=600000, DIM=128, int32 indices (confirmed R3).
//
// R4: EPW=4 -> 65.8us, DRAM 66%. Still latency-bound; ptxas kept only 38 regs
// (loads partially serialized). R5/R6: EPW=8, fully front-batched loads (24
// float4 LDGs/lane in flight, under the ~55/warp HW cap). Trade occupancy
// (~45%) for 2x MLP. (R5 bench was an infra failure; resubmitting unchanged.)
//
// Lane l owns float4 at column 4*l. All row reads coalesced (512B/warp).
// rel_emb streamed once -> __ldcs keeps the 51MB node table resident in L2.

#define DIM 128
#define EPW 8   // edges per warp

__global__ __launch_bounds__(256)
void distmult_kernel(const float* __restrict__ node_emb,
                     const float* __restrict__ rel_emb,
                     const int* __restrict__ src,
                     const int* __restrict__ dst,
                     float* __restrict__ out,
                     int n_edges,
                     int n_nodes) {
    int warp = (blockIdx.x * blockDim.x + threadIdx.x) >> 5;
    int lane = threadIdx.x & 31;
    long long ebase = (long long)warp * EPW;
    if (ebase >= n_edges) return;

    // Index loads (warp-uniform -> broadcast).
    int s[EPW], d[EPW];
    #pragma unroll
    for (int i = 0; i < EPW; i++) {
        long long e = ebase + i;
        if (e >= n_edges) e = n_edges - 1;        // tail guard (600000 % 8 == 0 anyway)
        int si = src[e], di = dst[e];
        s[i] = min(max(si, 0), n_nodes - 1);       // defensive clamp
        d[i] = min(max(di, 0), n_nodes - 1);
    }

    // Front-batch ALL 24 float4 loads before any consumption.
    float4 hv[EPW], tv[EPW], rv[EPW];
    #pragma unroll
    for (int i = 0; i < EPW; i++) {
        hv[i] = reinterpret_cast<const float4*>(node_emb + (long long)s[i] * DIM)[lane];
        tv[i] = reinterpret_cast<const float4*>(node_emb + (long long)d[i] * DIM)[lane];
        rv[i] = __ldcs(reinterpret_cast<const float4*>(rel_emb + (ebase + i) * DIM) + lane);
    }

    // Consume in load order.
    float acc[EPW];
    #pragma unroll
    for (int i = 0; i < EPW; i++) {
        acc[i] = hv[i].x * rv[i].x * tv[i].x
               + hv[i].y * rv[i].y * tv[i].y
               + hv[i].z * rv[i].z * tv[i].z
               + hv[i].w * rv[i].w * tv[i].w;
    }

    // 8 independent butterfly reductions, interleaved to pipeline SHFL latency.
    #pragma unroll
    for (int off = 16; off > 0; off >>= 1) {
        #pragma unroll
        for (int i = 0; i < EPW; i++)
            acc[i] += __shfl_xor_sync(0xffffffffu, acc[i], off);
    }

    // acc[i] uniform post-reduction; lane i stores edge i (coalesced 8-wide).
    if (lane < EPW) {
        long long e = ebase + lane;
        if (e < n_edges) {
            float v;
            switch (lane) {   // acc[] indexed by literal so it stays in regs
                case 0: v = acc[0]; break;
                case 1: v = acc[1]; break;
                case 2: v = acc[2]; break;
                case 3: v = acc[3]; break;
                case 4: v = acc[4]; break;
                case 5: v = acc[5]; break;
                case 6: v = acc[6]; break;
                default: v = acc[7]; break;
            }
            out[e] = v;
        }
    }
}

extern "C" void kernel_launch(void* const* d_in, const int* in_sizes, int n_in,
                              void* d_out, int out_size) {
    const float* node_emb = (const float*)d_in[0];
    const float* rel_emb  = (const float*)d_in[1];
    const int*   src      = (const int*)d_in[2];
    const int*   dst      = (const int*)d_in[3];
    float* out = (float*)d_out;

    int n_edges = in_sizes[1] / DIM;   // rel_emb [E,128]
    int n_nodes = in_sizes[0] / DIM;   // node_emb [N,128]

    int threads = 256;                               // 8 warps -> 64 edges/block
    int edges_per_block = (threads / 32) * EPW;
    int blocks = (n_edges + edges_per_block - 1) / edges_per_block;

    distmult_kernel<<<blocks, threads>>>(node_emb, rel_emb, src, dst, out,
                                         n_edges, n_nodes);
}